// round 17
// baseline (speedup 1.0000x reference)
#include <cuda_runtime.h>
#include <cstdint>

// Casual_Conv1D: 31 chained Conv1d(1,1,k=2) == one 32-tap FIR + scalar bias.
// R17: tensor-core formulation. y[16u+v] = sum_m Xw[u][m] * C[m][v] with
// Xw[u][m] = x[16u+m], C[m][v] = c[m-v] (banded). Per block: M=128, K=48,
// N=16 via mma.sync.m16n8k8.tf32 (20 mma/warp after static band skip).
// B-frags via shfl from the per-warp composed coef register (no C smem).
// x tf32-rounded at staging; stride-20 pad -> conflict-free A gathers.

#define B_    128
#define L_    16384
#define NL_   31
#define LOUT_ (L_ - NL_)          // 16353
#define TPB_  128
#define TILE_ 2048
#define PADN_ 2600                // phys(i) = i + 4*(i>>4); max 2595
#define PADO_ 2560                // outputs, same map; max 2555

__device__ __forceinline__ uint32_t tf32r(float f) {
    uint32_t u; asm("cvt.rna.tf32.f32 %0, %1;" : "=r"(u) : "f"(f)); return u;
}
__device__ __forceinline__ void mma_tf32(float* d, const uint32_t* a,
                                         uint32_t b0, uint32_t b1) {
    asm volatile(
        "mma.sync.aligned.m16n8k8.row.col.f32.tf32.tf32.f32 "
        "{%0,%1,%2,%3}, {%4,%5,%6,%7}, {%8,%9}, {%0,%1,%2,%3};"
        : "+f"(d[0]), "+f"(d[1]), "+f"(d[2]), "+f"(d[3])
        : "r"(a[0]), "r"(a[1]), "r"(a[2]), "r"(a[3]), "r"(b0), "r"(b1));
}

__global__ void __launch_bounds__(TPB_)
fir_kernel(const float* __restrict__ x, const float* __restrict__ W,
           const float* __restrict__ b, float* __restrict__ y) {
    __shared__ float sbuf[PADN_];     // tf32-rounded input tile
    __shared__ float sout[PADO_];     // fp32 output staging

    const int tid  = threadIdx.x;
    const int lane = tid & 31;
    const int w    = tid >> 5;
    const int gid  = lane >> 2;       // mma group id (row)
    const int t4   = lane & 3;        // mma thread-in-group (col)
    const int row  = blockIdx.y;
    const int tile0 = blockIdx.x * TILE_;
    const float* xrow = x + (size_t)row * L_ + tile0;
    const bool last = (blockIdx.x == 7);          // tile0 = 14336

    // ---- issue global loads first (latency overlaps compose) ----
    float4 v[4];
    #pragma unroll
    for (int j = 0; j < 4; ++j)
        v[j] = *reinterpret_cast<const float4*>(xrow + tid * 4 + j * 512);
    float4 ve;
    const bool edge = (tid >= 32 && tid < 40);
    if (edge)
        ve = last ? make_float4(0.f, 0.f, 0.f, 0.f)
                  : *reinterpret_cast<const float4*>(xrow + 2048 + (tid - 32) * 4);

    // ---- per-warp compose: lane k holds c[k]; all lanes hold bias d ----
    float c = (lane == 0) ? W[0] : ((lane == 1) ? W[1] : 0.0f);
    float d = b[0];
    #pragma unroll
    for (int i = 1; i < NL_; ++i) {
        const float w0 = W[2 * i], w1 = W[2 * i + 1];
        float cp = __shfl_up_sync(0xFFFFFFFFu, c, 1);
        if (lane == 0) cp = 0.0f;
        c = w0 * c + w1 * cp;
        d = (w0 + w1) * d + b[i];
    }
    const float ctf = __uint_as_float(tf32r(c));  // tf32-rounded coefficient

    // ---- stage tile, tf32-rounded, vector STS; phys(i) = i + 4*(i>>4) ----
    {
        float* sp = sbuf + tid * 4 + 4 * (tid >> 2);
        #pragma unroll
        for (int j = 0; j < 4; ++j) {
            float4 q = v[j];
            q.x = __uint_as_float(tf32r(q.x));
            q.y = __uint_as_float(tf32r(q.y));
            q.z = __uint_as_float(tf32r(q.z));
            q.w = __uint_as_float(tf32r(q.w));
            *reinterpret_cast<float4*>(sp + 640 * j) = q;
        }
    }
    if (edge) {
        const int e = tid - 32;
        float4 q = ve;
        q.x = __uint_as_float(tf32r(q.x));
        q.y = __uint_as_float(tf32r(q.y));
        q.z = __uint_as_float(tf32r(q.z));
        q.w = __uint_as_float(tf32r(q.w));
        *reinterpret_cast<float4*>(sbuf + 2560 + 4 * e + 4 * (e >> 2)) = q;
    }
    __syncthreads();

    // ---- banded GEMM: warp w owns rows u in [32w, 32w+32) ----
    // A[u][m] = xt[16u+m]: phys = 20u + m + 4*(m>>4); a-frag col = 8s+t4(+4)
    // => phys = pa + 320*mt + 160*(row+8) + 8s + 4*(s>>1) (+4), all imm.
    const uint32_t* pa = reinterpret_cast<const uint32_t*>(sbuf)
                       + 20 * (32 * w + gid) + t4;

    float acc[2][2][4];               // [mtile][ntile][reg], init = bias
    #pragma unroll
    for (int mt = 0; mt < 2; ++mt)
        #pragma unroll
        for (int nt = 0; nt < 2; ++nt)
            #pragma unroll
            for (int r = 0; r < 4; ++r)
                acc[mt][nt][r] = d;

    #pragma unroll
    for (int s = 0; s < 6; ++s) {
        uint32_t A0[2][4];
        const int ao = 8 * s + 4 * (s >> 1);
        #pragma unroll
        for (int mt = 0; mt < 2; ++mt) {
            A0[mt][0] = pa[320 * mt + ao];
            A0[mt][1] = pa[320 * mt + 160 + ao];
            A0[mt][2] = pa[320 * mt + ao + 4];
            A0[mt][3] = pa[320 * mt + 160 + ao + 4];
        }
        #pragma unroll
        for (int nt = 0; nt < 2; ++nt) {
            if (s >= nt && s <= nt + 4) {         // static band skip
                const int i0 = 8 * s + t4 - 8 * nt - gid;
                float b0f = __shfl_sync(0xFFFFFFFFu, ctf, i0 & 31);
                if ((unsigned)i0 > 31u) b0f = 0.0f;
                const int i1 = i0 + 4;
                float b1f = __shfl_sync(0xFFFFFFFFu, ctf, i1 & 31);
                if ((unsigned)i1 > 31u) b1f = 0.0f;
                const uint32_t b0 = __float_as_uint(b0f);
                const uint32_t b1 = __float_as_uint(b1f);
                mma_tf32(acc[0][nt], A0[0], b0, b1);
                mma_tf32(acc[1][nt], A0[1], b0, b1);
            }
        }
    }

    // ---- epilogue: d-frag (u = 32w+16mt+gid(+8), v = 8nt+2*t4+(r&1)) ----
    {
        float* so = sout + 20 * (32 * w + gid) + 2 * t4;
        #pragma unroll
        for (int mt = 0; mt < 2; ++mt)
            #pragma unroll
            for (int nt = 0; nt < 2; ++nt)
                #pragma unroll
                for (int r = 0; r < 4; ++r)
                    so[320 * mt + 160 * (r >> 1) + 8 * nt + (r & 1)]
                        = acc[mt][nt][r];
    }
    __syncwarp();                     // sout region is warp-private

    // ---- warp-local coalesced readout: i = 512w + lane + 32j ----
    float* yw = y + (size_t)row * LOUT_ + tile0 + 512 * w + lane;
    const float* sr = sout + 640 * w + lane + 4 * (lane >> 4);
    if (!last) {
        #pragma unroll
        for (int j = 0; j < 16; ++j)
            yw[j * 32] = sr[j * 40];
    } else {
        const int lim = 2017 - 512 * w;          // valid outputs this warp
        #pragma unroll
        for (int j = 0; j < 16; ++j)
            if (lane + j * 32 < lim)
                yw[j * 32] = sr[j * 40];
    }
}

// ---------------------------------------------------------------------------
extern "C" void kernel_launch(void* const* d_in, const int* in_sizes, int n_in,
                              void* d_out, int out_size) {
    const float* x = (const float*)d_in[0];   // (128, 1, 16384) f32
    const float* W = (const float*)d_in[1];   // (31, 2) f32
    const float* b = (const float*)d_in[2];   // (31,)  f32
    float* y = (float*)d_out;                 // (128, 1, 16353) f32

    dim3 grid(L_ / TILE_, B_);                // (8, 128) = 1024 blocks
    fir_kernel<<<grid, TPB_>>>(x, W, b, y);
}